// round 15
// baseline (speedup 1.0000x reference)
#include <cuda_runtime.h>

// ExponentialGlobalConv: out[b,m,c] = DX * sum_n x[b,n] * exp(-|n-m|*DX/w_c) / (2 w_c)
// Uniform grid => separable exponential (Laplace) kernel => fwd+bwd IIR scan:
//   S_f[m] = x[m] + r*S_f[m-1], S_b[m] = x[m] + r*S_b[m+1], r = exp(-DX/w)
//   out[m] = scale*(S_f[m] + S_b[m] - x[m]),  scale = DX/(2w)
//
// FINAL (locked; kernel 6.40-6.53us across 7 reproductions; bench noise +-0.4us):
// - 256 CTAs x 256 threads (8 warps), single wave, 2 CTAs/SM capable.
// - CTA stages its 24-chunk window (3KB) with one coalesced float4/thread
//   (zero-padded at row edges); all chunk reads are LDS broadcasts (lane=channel).
// - Uniform warp roles: each warp scans its own output chunk (fwd keeping Floc,
//   bwd in place) and fuses one fwd-halo + one bwd-halo end-only scan.
// - Seeds s,u = 8-term dot products over neighbor chunk end-sums (hop r^32).
// - Combine = 3 independent FMAs per element:
//     out[k] = fma(s, r^{k+1}, fma(u, r^{32-k}, fma(r, Floc[k-1], Bloc[k])))
// - Halo truncation (HALOC=8 ~ e^{-8.5} relative) => rel_err 1.95e-4 << 1e-3.
// Session evidence: kernel pinned at launch/ramp+issue floor; all pipes <13%;
// direct-LDG (L1tex flood, +7us), 2-wave grids (+1.3us), register-light and
// occupancy variants (neutral) bracket the floor from both sides.

#define NCH   32
#define NG    2048
#define NB    32
#define DXC   0.08f
#define CL    32
#define HALOC 8                   // halo chunks per side
#define OUTC  8                   // output chunks per block
#define WINCH (OUTC + 2*HALOC)    // 24 window chunks
#define NWARP 8
#define NTHREADS (NWARP * 32)     // 256
#define BPB   8                   // blocks per batch row

__global__ __launch_bounds__(NTHREADS, 2)
void egc_kernel(const float* __restrict__ x,
                const float* __restrict__ eta,
                float* __restrict__ out)
{
    __shared__ float xs[WINCH * CL];   // 3KB zero-padded window, chunks baseg..baseg+23
    __shared__ float ef[16][32];       // fwd end-sums, window chunks 0..15
    __shared__ float eb[16][32];       // bwd end-sums, window chunks 8..23 (idx wc-8)

    const int tid  = threadIdx.x;
    const int lane = tid & 31;              // channel
    const int w    = tid >> 5;              // warp 0..7
    const int b    = blockIdx.x >> 3;       // batch row
    const int q    = blockIdx.x & 7;        // eighth of grid dim
    const int baseg = q * OUTC - HALOC;     // global chunk at window wc=0

    // ---- stage window into smem: threads 0..191 load one float4, zero-padded ----
    if (tid < WINCH * CL / 4) {
        const float4* xrow4 = reinterpret_cast<const float4*>(x + (size_t)b * NG);
        const int g4 = baseg * (CL / 4) + tid;          // global float4 index
        float4 v = make_float4(0.f, 0.f, 0.f, 0.f);
        if (g4 >= 0 && g4 < NG / 4) v = xrow4[g4];
        reinterpret_cast<float4*>(xs)[tid] = v;
    }

    // ---- per-channel params (under load shadow) ----
    const float e     = eta[lane];
    const float sig   = 1.0f / (1.0f + __expf(-e));
    const float wid   = 0.1f + 4.9f * sig;
    const float r     = __expf(-DXC / wid);
    const float scale = DXC / (2.0f * wid);
    const float r2 = r * r, r3 = r2 * r, r4 = r2 * r2;

    // power table rp[k] = r^{k+1} (no cross-warp deps)
    float rp[CL];
    rp[0] = r; rp[1] = r2; rp[2] = r3; rp[3] = r4;
    #pragma unroll
    for (int k = 4; k < CL; k++) rp[k] = rp[k - 4] * r4;
    const float rL = rp[31];                 // r^32

    __syncthreads();

    // ---- own chunk (window 8+w) into regs, pre-scaled ----
    float ax[CL];
    {
        const float4* pa = reinterpret_cast<const float4*>(xs + (HALOC + w) * CL);
        #pragma unroll
        for (int i = 0; i < 8; i++) reinterpret_cast<float4*>(ax)[i] = pa[i];
    }
    #pragma unroll
    for (int k = 0; k < CL; k++) ax[k] *= scale;

    // ---- pass 1: own fwd chain (keep Floc) + fwd-halo end-scan (window chunk w) ----
    float Floc[CL];
    {
        const float* hx = xs + w * CL;
        float F = 0.f, E = 0.f;
        #pragma unroll
        for (int k = 0; k < CL; k++) {
            F = fmaf(r, F, ax[k]); Floc[k] = F;
            E = fmaf(r, E, hx[k]);               // scalar LDS broadcast
        }
        ef[HALOC + w][lane] = F;                 // own fwd end (scaled)
        ef[w][lane] = E * scale;                 // fwd halo end
    }

    // ---- pass 2: own bwd chain in place (Bloc := ax) + bwd-halo end-scan (wc 16+w) ----
    {
        const float* hx = xs + (16 + w) * CL;
        float Bw = 0.f, E = 0.f;
        #pragma unroll
        for (int k = CL - 1; k >= 0; k--) {
            Bw = fmaf(r, Bw, ax[k]); ax[k] = Bw;
            E = fmaf(r, E, hx[k]);
        }
        eb[w][lane] = Bw;                        // own bwd end (wc 8+w -> idx w)
        eb[8 + w][lane] = E * scale;             // bwd halo end (wc 16+w -> idx 8+w)
    }

    __syncthreads();

    // ---- seeds: 8-term dot products over neighbor end-sums ----
    float s = 0.f, u = 0.f;
    {
        float rLd = 1.0f;
        #pragma unroll
        for (int d = 1; d <= HALOC; d++) {
            s = fmaf(ef[HALOC + w - d][lane], rLd, s);
            u = fmaf(eb[w + d][lane],         rLd, u);
            rLd *= rL;
        }
    }

    // ---- combine + store: 3 independent FMAs per element ----
    float* op = out + ((size_t)b * NG + (size_t)(q * OUTC + w) * CL) * NCH + lane;
    op[0] = fmaf(s, rp[0], fmaf(u, rp[31], ax[0]));
    #pragma unroll
    for (int k = 1; k < CL; k++) {
        const float t = fmaf(r, Floc[k - 1], ax[k]);
        op[(size_t)k * NCH] = fmaf(s, rp[k], fmaf(u, rp[31 - k], t));
    }
}

extern "C" void kernel_launch(void* const* d_in, const int* in_sizes, int n_in,
                              void* d_out, int out_size)
{
    const float* x   = (const float*)d_in[0];  // inputs (32, 2048)
    // d_in[1] = grids (unused: uniform grid, spacing DX by construction)
    const float* eta = (const float*)d_in[2];  // eta (32,)
    float* out = (float*)d_out;                // (32, 2048, 32) fp32

    egc_kernel<<<NB * BPB, NTHREADS>>>(x, eta, out);
}

// round 16
// speedup vs baseline: 1.3413x; 1.3413x over previous
#include <cuda_runtime.h>

// ExponentialGlobalConv: out[b,m,c] = DX * sum_n x[b,n] * exp(-|n-m|*DX/w_c) / (2 w_c)
// Uniform grid => separable exponential (Laplace) kernel => fwd+bwd IIR scan:
//   S_f[m] = x[m] + r*S_f[m-1], S_b[m] = x[m] + r*S_b[m+1], r = exp(-DX/w)
//   out[m] = scale*(S_f[m] + S_b[m] - x[m]),  scale = DX/(2w)
//
// R16 = R13 with the scan section fused into ONE loop of FOUR independent
// 32-step FMA chains (fwd own -> Floc, bwd own -> Bloc, fwd halo, bwd halo).
// R13 ran them as two sequential 2-chain loops (latency-bound, ~2x64cyc serial);
// 4-way chain ILP fully covers the 4-cycle FMA latency, making the scan
// issue-bound. Tests the last untested hypothesis: does per-warp chain latency
// contribute to the 6.4-6.5us kernel floor?
// Everything else identical to the locked config (seeds = 8-term dot products,
// 3-FMA combine, 3KB staged window, single wave, HALOC=8 => rel_err 1.95e-4).

#define NCH   32
#define NG    2048
#define NB    32
#define DXC   0.08f
#define CL    32
#define HALOC 8                   // halo chunks per side
#define OUTC  8                   // output chunks per block
#define WINCH (OUTC + 2*HALOC)    // 24 window chunks
#define NWARP 8
#define NTHREADS (NWARP * 32)     // 256
#define BPB   8                   // blocks per batch row

__global__ __launch_bounds__(NTHREADS, 2)
void egc_kernel(const float* __restrict__ x,
                const float* __restrict__ eta,
                float* __restrict__ out)
{
    __shared__ float xs[WINCH * CL];   // 3KB zero-padded window, chunks baseg..baseg+23
    __shared__ float ef[16][32];       // fwd end-sums, window chunks 0..15
    __shared__ float eb[16][32];       // bwd end-sums, window chunks 8..23 (idx wc-8)

    const int tid  = threadIdx.x;
    const int lane = tid & 31;              // channel
    const int w    = tid >> 5;              // warp 0..7
    const int b    = blockIdx.x >> 3;       // batch row
    const int q    = blockIdx.x & 7;        // eighth of grid dim
    const int baseg = q * OUTC - HALOC;     // global chunk at window wc=0

    // ---- stage window into smem: threads 0..191 load one float4, zero-padded ----
    if (tid < WINCH * CL / 4) {
        const float4* xrow4 = reinterpret_cast<const float4*>(x + (size_t)b * NG);
        const int g4 = baseg * (CL / 4) + tid;          // global float4 index
        float4 v = make_float4(0.f, 0.f, 0.f, 0.f);
        if (g4 >= 0 && g4 < NG / 4) v = xrow4[g4];
        reinterpret_cast<float4*>(xs)[tid] = v;
    }

    // ---- per-channel params (under load shadow) ----
    const float e     = eta[lane];
    const float sig   = 1.0f / (1.0f + __expf(-e));
    const float wid   = 0.1f + 4.9f * sig;
    const float r     = __expf(-DXC / wid);
    const float scale = DXC / (2.0f * wid);
    const float r2 = r * r, r3 = r2 * r, r4 = r2 * r2;

    // power table rp[k] = r^{k+1} (no cross-warp deps)
    float rp[CL];
    rp[0] = r; rp[1] = r2; rp[2] = r3; rp[3] = r4;
    #pragma unroll
    for (int k = 4; k < CL; k++) rp[k] = rp[k - 4] * r4;
    const float rL = rp[31];                 // r^32

    __syncthreads();

    // ---- own chunk (window 8+w) into regs, pre-scaled ----
    float ax[CL];
    {
        const float4* pa = reinterpret_cast<const float4*>(xs + (HALOC + w) * CL);
        #pragma unroll
        for (int i = 0; i < 8; i++) reinterpret_cast<float4*>(ax)[i] = pa[i];
    }
    #pragma unroll
    for (int k = 0; k < CL; k++) ax[k] *= scale;

    // ---- fused scan: FOUR independent 32-step chains in one loop ----
    //   F  : fwd own  (reads ax ascending,  writes Floc)
    //   Bw : bwd own  (reads ax descending, writes Bloc)
    //   E  : fwd halo end-only (window chunk w)
    //   E2 : bwd halo end-only (window chunk 16+w)
    float Floc[CL], Bloc[CL];
    {
        const float* hf = xs + w * CL;
        const float* hb = xs + (16 + w) * CL;
        float F = 0.f, Bw = 0.f, E = 0.f, E2 = 0.f;
        #pragma unroll
        for (int k = 0; k < CL; k++) {
            const int kr = CL - 1 - k;
            F  = fmaf(r, F,  ax[k]);  Floc[k]  = F;
            Bw = fmaf(r, Bw, ax[kr]); Bloc[kr] = Bw;
            E  = fmaf(r, E,  hf[k]);
            E2 = fmaf(r, E2, hb[kr]);
        }
        ef[HALOC + w][lane] = F;                 // own fwd end (scaled)
        eb[w][lane]         = Bw;                // own bwd end (wc 8+w -> idx w)
        ef[w][lane]         = E  * scale;        // fwd halo end
        eb[8 + w][lane]     = E2 * scale;        // bwd halo end (wc 16+w -> idx 8+w)
    }

    __syncthreads();

    // ---- seeds: 8-term dot products over neighbor end-sums ----
    float s = 0.f, u = 0.f;
    {
        float rLd = 1.0f;
        #pragma unroll
        for (int d = 1; d <= HALOC; d++) {
            s = fmaf(ef[HALOC + w - d][lane], rLd, s);
            u = fmaf(eb[w + d][lane],         rLd, u);
            rLd *= rL;
        }
    }

    // ---- combine + store: 3 independent FMAs per element ----
    float* op = out + ((size_t)b * NG + (size_t)(q * OUTC + w) * CL) * NCH + lane;
    op[0] = fmaf(s, rp[0], fmaf(u, rp[31], Bloc[0]));
    #pragma unroll
    for (int k = 1; k < CL; k++) {
        const float t = fmaf(r, Floc[k - 1], Bloc[k]);
        op[(size_t)k * NCH] = fmaf(s, rp[k], fmaf(u, rp[31 - k], t));
    }
}

extern "C" void kernel_launch(void* const* d_in, const int* in_sizes, int n_in,
                              void* d_out, int out_size)
{
    const float* x   = (const float*)d_in[0];  // inputs (32, 2048)
    // d_in[1] = grids (unused: uniform grid, spacing DX by construction)
    const float* eta = (const float*)d_in[2];  // eta (32,)
    float* out = (float*)d_out;                // (32, 2048, 32) fp32

    egc_kernel<<<NB * BPB, NTHREADS>>>(x, eta, out);
}